// round 15
// baseline (speedup 1.0000x reference)
#include <cuda_runtime.h>
#include <cuda_bf16.h>
#include <cstdint>

// ---------------- device scratch (no allocations allowed) ----------------
#define N_NODES 50000
#define E_MAX   800000
#define SCAN_B  256
#define NSB     ((N_NODES + SCAN_B - 1) / SCAN_B)   // 196

// bf16 hi/lo planes: [node][64] u32 (pair-packed), 12.8 MB each
__device__ uint32_t g_fhi[(size_t)N_NODES * 64];
__device__ uint32_t g_flo[(size_t)N_NODES * 64];
__device__ uint32_t g_nhi[(size_t)N_NODES * 64];
__device__ uint32_t g_nlo[(size_t)N_NODES * 64];
__device__ float g_stats[256];                        // colsum / colsumsq
// CSR build
__device__ int   g_cnt[N_NODES];
__device__ int   g_rowptr[N_NODES + 1];
__device__ int   g_fill[N_NODES];
__device__ int   g_bsum[NSB];
__device__ uint2 g_epack[E_MAX];                      // (src, w-bits)
// W fragment table: [part(hi/lo)][k16 0..15][ntile 0..15][lane 0..31] = uint2
__device__ uint2 g_wfrag[2 * 16 * 16 * 32];

// ---------------- helpers ----------------
__device__ __forceinline__ uint32_t pack_bf16(float a, float b) {
    __nv_bfloat16 ha = __float2bfloat16(a);
    __nv_bfloat16 hb = __float2bfloat16(b);
    return (uint32_t)__bfloat16_as_ushort(ha) |
           ((uint32_t)__bfloat16_as_ushort(hb) << 16);
}
// fast packed split: 6 instructions per float2
__device__ __forceinline__ void cvt_hilo_fast(float2 v, uint32_t& hi, uint32_t& lo) {
    uint32_t hip;
    asm("cvt.rn.bf16x2.f32 %0, %1, %2;" : "=r"(hip) : "f"(v.y), "f"(v.x));
    float r0 = v.x - __uint_as_float(hip << 16);
    float r1 = v.y - __uint_as_float(hip & 0xFFFF0000u);
    uint32_t lop;
    asm("cvt.rn.bf16x2.f32 %0, %1, %2;" : "=r"(lop) : "f"(r1), "f"(r0));
    hi = hip; lo = lop;
}

#define MMA16816(d, a, b0v, b1v)                                             \
    asm volatile(                                                            \
        "mma.sync.aligned.m16n8k16.row.col.f32.bf16.bf16.f32 "               \
        "{%0,%1,%2,%3}, {%4,%5,%6,%7}, {%8,%9}, {%0,%1,%2,%3};"              \
        : "+f"((d)[0]), "+f"((d)[1]), "+f"((d)[2]), "+f"((d)[3])             \
        : "r"((a)[0]), "r"((a)[1]), "r"((a)[2]), "r"((a)[3]),                \
          "r"(b0v), "r"(b1v))

// ---------------- kernel 1: init (zero + W prep + feat bf16 planes) --------
__global__ void k_init(const float* __restrict__ feat,
                       const float* __restrict__ Wneigh,
                       const float* __restrict__ Wself, int N) {
    int b = blockIdx.x;
    if (b < NSB) {
        int i = b * 256 + threadIdx.x;
        if (i < N) g_cnt[i] = 0;
        if (i < 256) g_stats[i] = 0.f;
        return;
    }
    if (b < NSB + 64) {
        int t = (b - NSB) * 256 + threadIdx.x;   // 0..16383
        if (t >= 16384) return;
        int part = t >> 13;
        int ks   = (t >> 9) & 15;
        int nt   = (t >> 5) & 15;
        int lane = t & 31;
        int n  = nt * 8 + (lane >> 2);
        int k0 = ks * 16 + (lane & 3) * 2;
        const float* W = (k0 < 128) ? Wself : Wneigh;
        int kk = k0 & 127;
        float w0 = W[n * 128 + kk];
        float w1 = W[n * 128 + kk + 1];
        float w2 = W[n * 128 + kk + 8];
        float w3 = W[n * 128 + kk + 9];
        uint2 v;
        if (part == 0) {
            v.x = pack_bf16(w0, w1);
            v.y = pack_bf16(w2, w3);
        } else {
            float h0 = __bfloat162float(__float2bfloat16(w0));
            float h1 = __bfloat162float(__float2bfloat16(w1));
            float h2 = __bfloat162float(__float2bfloat16(w2));
            float h3 = __bfloat162float(__float2bfloat16(w3));
            v.x = pack_bf16(w0 - h0, w1 - h1);
            v.y = pack_bf16(w2 - h2, w3 - h3);
        }
        g_wfrag[((part * 16 + ks) * 16 + nt) * 32 + lane] = v;
        return;
    }
    // feat -> bf16 hi/lo planes, one float2 per thread
    int idx = (b - NSB - 64) * 256 + threadIdx.x;
    if (idx >= N * 64) return;
    float2 v = ((const float2*)feat)[idx];
    uint32_t hi, lo;
    cvt_hilo_fast(v, hi, lo);
    g_fhi[idx] = hi;
    g_flo[idx] = lo;
}

// ---------------- kernel 2: histogram of dst ----------------
__global__ void k_hist(const int* __restrict__ dst, int E) {
    int e = blockIdx.x * blockDim.x + threadIdx.x;
    if (e < E) atomicAdd(&g_cnt[__ldg(dst + e)], 1);
}

// ---------------- kernel 3a: per-block sums ----------------
__global__ void k_scan1(int N) {
    __shared__ int sp[SCAN_B];
    int idx = blockIdx.x * SCAN_B + threadIdx.x;
    int v = (idx < N) ? g_cnt[idx] : 0;
    sp[threadIdx.x] = v;
    __syncthreads();
    for (int off = SCAN_B / 2; off > 0; off >>= 1) {
        if (threadIdx.x < off) sp[threadIdx.x] += sp[threadIdx.x + off];
        __syncthreads();
    }
    if (threadIdx.x == 0) g_bsum[blockIdx.x] = sp[0];
}

// ---------------- kernel 3b: merged block-sum scan + local scan ------------
__global__ void k_scan23(int N, int E) {
    __shared__ int sb[NSB];
    __shared__ int sp[SCAN_B];
    int tid = threadIdx.x;
    // every block scans the 196 block sums (cheap, removes a launch)
    int bv = (tid < NSB) ? g_bsum[tid] : 0;
    if (tid < NSB) sb[tid] = bv;
    __syncthreads();
    for (int off = 1; off < NSB; off <<= 1) {
        int t = (tid < NSB && tid >= off) ? sb[tid - off] : 0;
        __syncthreads();
        if (tid < NSB) sb[tid] += t;
        __syncthreads();
    }
    int boff = (blockIdx.x == 0) ? 0 : sb[blockIdx.x - 1];
    int idx = blockIdx.x * SCAN_B + tid;
    int v = (idx < N) ? g_cnt[idx] : 0;
    sp[tid] = v;
    __syncthreads();
    for (int off = 1; off < SCAN_B; off <<= 1) {
        int t = (tid >= off) ? sp[tid - off] : 0;
        __syncthreads();
        sp[tid] += t;
        __syncthreads();
    }
    if (idx < N) {
        int r = boff + sp[tid] - v;
        g_rowptr[idx] = r;
        g_fill[idx] = r;
    }
    if (blockIdx.x == 0 && tid == 0) g_rowptr[N] = E;
}

// ---------------- kernel 4: place edges (packed uint2) ----------------
__global__ void k_place(const int* __restrict__ src,
                        const int* __restrict__ dst,
                        const float* __restrict__ ew,
                        int E) {
    int e = blockIdx.x * blockDim.x + threadIdx.x;
    if (e >= E) return;
    int d = __ldg(dst + e);
    int pos = atomicAdd(&g_fill[d], 1);
    g_epack[pos] = make_uint2((uint32_t)__ldg(src + e),
                              __float_as_uint(__ldg(ew + e)));
}

// ---------------- kernel 5: warp-per-node gather + normalize + bf16 split --
__global__ void __launch_bounds__(256)
k_agg(const float* __restrict__ feat, int N) {
    int n = blockIdx.x * 8 + (threadIdx.x >> 5);
    if (n >= N) return;
    int lane = threadIdx.x & 31;
    int b = g_rowptr[n];
    int eend = g_rowptr[n + 1];
    float4 acc = {0.f, 0.f, 0.f, 0.f};
    float ws = 0.f;
    int e = b;
    for (; e + 1 < eend; e += 2) {
        uint2 p0 = g_epack[e];
        uint2 p1 = g_epack[e + 1];
        float w0 = __uint_as_float(p0.y);
        float w1 = __uint_as_float(p1.y);
        float4 v0 = __ldg((const float4*)feat + (size_t)p0.x * 32 + lane);
        float4 v1 = __ldg((const float4*)feat + (size_t)p1.x * 32 + lane);
        acc.x += w0 * v0.x + w1 * v1.x;
        acc.y += w0 * v0.y + w1 * v1.y;
        acc.z += w0 * v0.z + w1 * v1.z;
        acc.w += w0 * v0.w + w1 * v1.w;
        ws += w0 + w1;
    }
    if (e < eend) {
        uint2 p0 = g_epack[e];
        float w0 = __uint_as_float(p0.y);
        float4 v0 = __ldg((const float4*)feat + (size_t)p0.x * 32 + lane);
        acc.x += w0 * v0.x;
        acc.y += w0 * v0.y;
        acc.z += w0 * v0.z;
        acc.w += w0 * v0.w;
        ws += w0;
    }
    float inv = 1.0f / (ws + 1e-8f);   // ws is warp-uniform
    acc.x *= inv; acc.y *= inv; acc.z *= inv; acc.w *= inv;
    uint32_t h0, l0, h1, l1;
    cvt_hilo_fast(make_float2(acc.x, acc.y), h0, l0);
    cvt_hilo_fast(make_float2(acc.z, acc.w), h1, l1);
    ((uint2*)g_nhi)[(size_t)n * 32 + lane] = make_uint2(h0, h1);
    ((uint2*)g_nlo)[(size_t)n * 32 + lane] = make_uint2(l0, l1);
}

// ---------------- kernel 6: pipelined mma.sync GEMM (copy-only staging) ----
// 512 threads (16 warps: 8 M x 2 N), tile 128x128, K=256 in 4 chunks of 64.
#define XS_STRIDE 36
#define XBUF_U32  (128 * XS_STRIDE)          // 4608 u32 per (hi|lo) plane
#define GEMM_SMEM (2 * 2 * XBUF_U32 * 4)     // 73728 bytes

__global__ void __launch_bounds__(512)
k_gemm_mma(const float* __restrict__ b_self,
           const float* __restrict__ bias,
           float* __restrict__ out,
           int N) {
    extern __shared__ uint32_t sx[];
    __shared__ float s_sum[128], s_ssq[128];
    int tid  = threadIdx.x;
    int wid  = tid >> 5;
    int lane = tid & 31;
    int wm   = wid & 7;
    int wn   = wid >> 3;
    int n0   = blockIdx.x * 128;
    int g    = lane >> 2;
    int c    = lane & 3;

    if (tid < 128) { s_sum[tid] = 0.f; s_ssq[tid] = 0.f; }

    float acc[8][4];
#pragma unroll
    for (int nt = 0; nt < 8; ++nt)
#pragma unroll
        for (int q = 0; q < 4; ++q) acc[nt][q] = 0.f;

    uint4 pv[2][2];   // [it][plane]

    auto stage_load = [&](int kc) {
        const uint4* ph = (const uint4*)((kc < 2) ? g_fhi : g_nhi);
        const uint4* pl = (const uint4*)((kc < 2) ? g_flo : g_nlo);
        int cb4 = (kc & 1) * 8;
#pragma unroll
        for (int it = 0; it < 2; ++it) {
            int idx = tid + it * 512;
            int row = idx >> 3, qc = idx & 7;
            int gn = n0 + row;
            if (gn < N) {
                size_t o = (size_t)gn * 16 + cb4 + qc;
                pv[it][0] = ph[o];
                pv[it][1] = pl[o];
            } else {
                pv[it][0] = make_uint4(0, 0, 0, 0);
                pv[it][1] = make_uint4(0, 0, 0, 0);
            }
        }
    };
    auto stage_store = [&](uint32_t* bh, uint32_t* bl) {
#pragma unroll
        for (int it = 0; it < 2; ++it) {
            int idx = tid + it * 512;
            int row = idx >> 3, qc = idx & 7;
            *(uint4*)(bh + row * XS_STRIDE + qc * 4) = pv[it][0];
            *(uint4*)(bl + row * XS_STRIDE + qc * 4) = pv[it][1];
        }
    };
    auto compute = [&](int kc, const uint32_t* bh, const uint32_t* bl) {
#pragma unroll
        for (int j = 0; j < 4; ++j) {
            uint32_t ahi[4], alo[4];
            int r0 = (wm * 16 + g) * XS_STRIDE + j * 8;
            ahi[0] = bh[r0 + c];
            ahi[1] = bh[r0 + 8 * XS_STRIDE + c];
            ahi[2] = bh[r0 + c + 4];
            ahi[3] = bh[r0 + 8 * XS_STRIDE + c + 4];
            alo[0] = bl[r0 + c];
            alo[1] = bl[r0 + 8 * XS_STRIDE + c];
            alo[2] = bl[r0 + c + 4];
            alo[3] = bl[r0 + 8 * XS_STRIDE + c + 4];
            int ks = kc * 4 + j;
#pragma unroll
            for (int nt = 0; nt < 8; ++nt) {
                uint2 bhi = __ldg(&g_wfrag[((0 * 16 + ks) * 16 + wn * 8 + nt) * 32 + lane]);
                uint2 blo = __ldg(&g_wfrag[((1 * 16 + ks) * 16 + wn * 8 + nt) * 32 + lane]);
                MMA16816(acc[nt], ahi, bhi.x, bhi.y);
                MMA16816(acc[nt], ahi, blo.x, blo.y);
                MMA16816(acc[nt], alo, bhi.x, bhi.y);
            }
        }
    };

    uint32_t* buf0 = sx;
    uint32_t* buf1 = sx + 2 * XBUF_U32;

    stage_load(0);
    stage_store(buf0, buf0 + XBUF_U32);
    __syncthreads();

#pragma unroll
    for (int kc = 0; kc < 4; ++kc) {
        uint32_t* cb = (kc & 1) ? buf1 : buf0;
        uint32_t* nb = (kc & 1) ? buf0 : buf1;
        if (kc < 3) stage_load(kc + 1);
        compute(kc, cb, cb + XBUF_U32);
        if (kc < 3) {
            stage_store(nb, nb + XBUF_U32);
            __syncthreads();
        }
    }

    // ---- epilogue: bias + relu + store + fused BN stats ----
    float2 bsum[8];
#pragma unroll
    for (int nt = 0; nt < 8; ++nt) {
        int p = wn * 32 + nt * 4 + c;
        float2 b1 = __ldg((const float2*)b_self + p);
        float2 b2 = __ldg((const float2*)bias + p);
        bsum[nt].x = b1.x + b2.x;
        bsum[nt].y = b1.y + b2.y;
    }
    int r0 = n0 + wm * 16 + g;
    int r1 = r0 + 8;
#pragma unroll
    for (int nt = 0; nt < 8; ++nt) {
        int p = wn * 32 + nt * 4 + c;
        float cs0 = 0.f, cs1 = 0.f, cq0 = 0.f, cq1 = 0.f;
        if (r0 < N) {
            float2 v;
            v.x = fmaxf(acc[nt][0] + bsum[nt].x, 0.f);
            v.y = fmaxf(acc[nt][1] + bsum[nt].y, 0.f);
            ((float2*)out)[(size_t)r0 * 64 + p] = v;
            cs0 += v.x; cs1 += v.y;
            cq0 += v.x * v.x; cq1 += v.y * v.y;
        }
        if (r1 < N) {
            float2 v;
            v.x = fmaxf(acc[nt][2] + bsum[nt].x, 0.f);
            v.y = fmaxf(acc[nt][3] + bsum[nt].y, 0.f);
            ((float2*)out)[(size_t)r1 * 64 + p] = v;
            cs0 += v.x; cs1 += v.y;
            cq0 += v.x * v.x; cq1 += v.y * v.y;
        }
        atomicAdd(&s_sum[p * 2], cs0);
        atomicAdd(&s_sum[p * 2 + 1], cs1);
        atomicAdd(&s_ssq[p * 2], cq0);
        atomicAdd(&s_ssq[p * 2 + 1], cq1);
    }
    __syncthreads();
    if (tid < 128) {
        atomicAdd(&g_stats[tid], s_sum[tid]);
        atomicAdd(&g_stats[128 + tid], s_ssq[tid]);
    }
}

// ---------------- kernel 7: apply BN (scale/shift computed in-block) -------
__global__ void k_apply(float* __restrict__ out, int n4,
                        const float* __restrict__ gamma,
                        const float* __restrict__ beta,
                        float invN) {
    __shared__ float4 ssc[32], ssh[32];
    int tid = threadIdx.x;
    if (tid < 32) {
        float4 sc, sh;
        float* scp = (float*)&sc;
        float* shp = (float*)&sh;
#pragma unroll
        for (int q = 0; q < 4; ++q) {
            int col = tid * 4 + q;
            float mu  = g_stats[col] * invN;
            float var = fmaxf(g_stats[128 + col] * invN - mu * mu, 0.f);
            float s   = __ldg(gamma + col) * rsqrtf(var + 1e-5f);
            scp[q] = s;
            shp[q] = __ldg(beta + col) - mu * s;
        }
        ssc[tid] = sc;
        ssh[tid] = sh;
    }
    __syncthreads();
    int i = blockIdx.x * blockDim.x + tid;
    if (i >= n4) return;
    int c = i & 31;
    float4 v  = ((float4*)out)[i];
    float4 sc = ssc[c];
    float4 sh = ssh[c];
    v.x = fmaf(v.x, sc.x, sh.x);
    v.y = fmaf(v.y, sc.y, sh.y);
    v.z = fmaf(v.z, sc.z, sh.z);
    v.w = fmaf(v.w, sc.w, sh.w);
    ((float4*)out)[i] = v;
}

// ---------------- launch ----------------
extern "C" void kernel_launch(void* const* d_in, const int* in_sizes, int n_in,
                              void* d_out, int out_size) {
    const float* feat   = (const float*)d_in[0];
    const int*   src    = (const int*)d_in[1];
    const int*   dst    = (const int*)d_in[2];
    const float* ew     = (const float*)d_in[3];
    const float* Wneigh = (const float*)d_in[4];
    const float* Wself  = (const float*)d_in[5];
    const float* b_self = (const float*)d_in[6];
    const float* bias   = (const float*)d_in[7];
    const float* gamma  = (const float*)d_in[8];
    const float* beta   = (const float*)d_in[9];
    float* out = (float*)d_out;

    int N = in_sizes[0] / 128;
    int E = in_sizes[1];

    cudaFuncSetAttribute(k_gemm_mma, cudaFuncAttributeMaxDynamicSharedMemorySize,
                         GEMM_SMEM);

    int cvt_blocks = (N * 64 + 255) / 256;
    k_init<<<NSB + 64 + cvt_blocks, 256>>>(feat, Wneigh, Wself, N);
    k_hist<<<(E + 255) / 256, 256>>>(dst, E);
    k_scan1<<<NSB, SCAN_B>>>(N);
    k_scan23<<<NSB, SCAN_B>>>(N, E);
    k_place<<<(E + 255) / 256, 256>>>(src, dst, ew, E);
    k_agg<<<(N + 7) / 8, 256>>>(feat, N);
    k_gemm_mma<<<(N + 127) / 128, 512, GEMM_SMEM>>>(b_self, bias, out, N);
    k_apply<<<(N * 32 + 255) / 256, 256>>>(out, N * 32, gamma, beta,
                                           1.0f / (float)N);
}

// round 16
// speedup vs baseline: 1.4869x; 1.4869x over previous
#include <cuda_runtime.h>
#include <cuda_bf16.h>
#include <cstdint>

// ---------------- device scratch (no allocations allowed) ----------------
#define N_NODES 50000
#define E_MAX   800000
#define SCAN_B  256
#define NSB     ((N_NODES + SCAN_B - 1) / SCAN_B)   // 196

// normalized-neighbor bf16 hi/lo planes: [node][64] u32 (pair-packed)
__device__ uint32_t g_nhi[(size_t)N_NODES * 64];
__device__ uint32_t g_nlo[(size_t)N_NODES * 64];
__device__ float g_stats[256];                        // colsum / colsumsq
// CSR build
__device__ int   g_cnt[N_NODES];
__device__ int   g_rowptr[N_NODES + 1];
__device__ int   g_fill[N_NODES];
__device__ int   g_bsum[NSB];
__device__ uint2 g_epack[E_MAX];                      // (src, w-bits)
// W fragment table: [part(hi/lo)][k16 0..15][ntile 0..15][lane 0..31] = uint2
__device__ uint2 g_wfrag[2 * 16 * 16 * 32];

// ---------------- helpers ----------------
__device__ __forceinline__ uint32_t pack_bf16(float a, float b) {
    __nv_bfloat16 ha = __float2bfloat16(a);
    __nv_bfloat16 hb = __float2bfloat16(b);
    return (uint32_t)__bfloat16_as_ushort(ha) |
           ((uint32_t)__bfloat16_as_ushort(hb) << 16);
}
// fast packed split: ~6 instructions per float2
__device__ __forceinline__ void cvt_hilo_fast(float2 v, uint32_t& hi, uint32_t& lo) {
    uint32_t hip;
    asm("cvt.rn.bf16x2.f32 %0, %1, %2;" : "=r"(hip) : "f"(v.y), "f"(v.x));
    float r0 = v.x - __uint_as_float(hip << 16);
    float r1 = v.y - __uint_as_float(hip & 0xFFFF0000u);
    uint32_t lop;
    asm("cvt.rn.bf16x2.f32 %0, %1, %2;" : "=r"(lop) : "f"(r1), "f"(r0));
    hi = hip; lo = lop;
}

#define MMA16816(d, a, b0v, b1v)                                             \
    asm volatile(                                                            \
        "mma.sync.aligned.m16n8k16.row.col.f32.bf16.bf16.f32 "               \
        "{%0,%1,%2,%3}, {%4,%5,%6,%7}, {%8,%9}, {%0,%1,%2,%3};"              \
        : "+f"((d)[0]), "+f"((d)[1]), "+f"((d)[2]), "+f"((d)[3])             \
        : "r"((a)[0]), "r"((a)[1]), "r"((a)[2]), "r"((a)[3]),                \
          "r"(b0v), "r"(b1v))

// ---------------- kernel 1: init (zero + W fragment prep) ----------------
__global__ void k_init(const float* __restrict__ Wneigh,
                       const float* __restrict__ Wself, int N) {
    int b = blockIdx.x;
    if (b < NSB) {
        int i = b * 256 + threadIdx.x;
        if (i < N) g_cnt[i] = 0;
        if (i < 256) g_stats[i] = 0.f;
        return;
    }
    int t = (b - NSB) * 256 + threadIdx.x;   // 0..16383
    if (t >= 16384) return;
    int part = t >> 13;
    int ks   = (t >> 9) & 15;
    int nt   = (t >> 5) & 15;
    int lane = t & 31;
    int n  = nt * 8 + (lane >> 2);
    int k0 = ks * 16 + (lane & 3) * 2;
    const float* W = (k0 < 128) ? Wself : Wneigh;
    int kk = k0 & 127;
    float w0 = W[n * 128 + kk];
    float w1 = W[n * 128 + kk + 1];
    float w2 = W[n * 128 + kk + 8];
    float w3 = W[n * 128 + kk + 9];
    uint2 v;
    if (part == 0) {
        v.x = pack_bf16(w0, w1);
        v.y = pack_bf16(w2, w3);
    } else {
        float h0 = __bfloat162float(__float2bfloat16(w0));
        float h1 = __bfloat162float(__float2bfloat16(w1));
        float h2 = __bfloat162float(__float2bfloat16(w2));
        float h3 = __bfloat162float(__float2bfloat16(w3));
        v.x = pack_bf16(w0 - h0, w1 - h1);
        v.y = pack_bf16(w2 - h2, w3 - h3);
    }
    g_wfrag[((part * 16 + ks) * 16 + nt) * 32 + lane] = v;
}

// ---------------- kernel 2: histogram of dst ----------------
__global__ void k_hist(const int* __restrict__ dst, int E) {
    int e = blockIdx.x * blockDim.x + threadIdx.x;
    if (e < E) atomicAdd(&g_cnt[__ldg(dst + e)], 1);
}

// ---------------- kernel 3a: per-block sums ----------------
__global__ void k_scan1(int N) {
    __shared__ int sp[SCAN_B];
    int idx = blockIdx.x * SCAN_B + threadIdx.x;
    int v = (idx < N) ? g_cnt[idx] : 0;
    sp[threadIdx.x] = v;
    __syncthreads();
    for (int off = SCAN_B / 2; off > 0; off >>= 1) {
        if (threadIdx.x < off) sp[threadIdx.x] += sp[threadIdx.x + off];
        __syncthreads();
    }
    if (threadIdx.x == 0) g_bsum[blockIdx.x] = sp[0];
}

// ---------------- kernel 3b: merged block-sum scan + local scan ------------
__global__ void k_scan23(int N, int E) {
    __shared__ int sb[NSB];
    __shared__ int sp[SCAN_B];
    int tid = threadIdx.x;
    int bv = (tid < NSB) ? g_bsum[tid] : 0;
    if (tid < NSB) sb[tid] = bv;
    __syncthreads();
    for (int off = 1; off < NSB; off <<= 1) {
        int t = (tid < NSB && tid >= off) ? sb[tid - off] : 0;
        __syncthreads();
        if (tid < NSB) sb[tid] += t;
        __syncthreads();
    }
    int boff = (blockIdx.x == 0) ? 0 : sb[blockIdx.x - 1];
    int idx = blockIdx.x * SCAN_B + tid;
    int v = (idx < N) ? g_cnt[idx] : 0;
    sp[tid] = v;
    __syncthreads();
    for (int off = 1; off < SCAN_B; off <<= 1) {
        int t = (tid >= off) ? sp[tid - off] : 0;
        __syncthreads();
        sp[tid] += t;
        __syncthreads();
    }
    if (idx < N) {
        int r = boff + sp[tid] - v;
        g_rowptr[idx] = r;
        g_fill[idx] = r;
    }
    if (blockIdx.x == 0 && tid == 0) g_rowptr[N] = E;
}

// ---------------- kernel 4: place edges (packed uint2) ----------------
__global__ void k_place(const int* __restrict__ src,
                        const int* __restrict__ dst,
                        const float* __restrict__ ew,
                        int E) {
    int e = blockIdx.x * blockDim.x + threadIdx.x;
    if (e >= E) return;
    int d = __ldg(dst + e);
    int pos = atomicAdd(&g_fill[d], 1);
    g_epack[pos] = make_uint2((uint32_t)__ldg(src + e),
                              __float_as_uint(__ldg(ew + e)));
}

// ---------------- kernel 5: warp-per-node gather + normalize + bf16 split --
__global__ void __launch_bounds__(256)
k_agg(const float* __restrict__ feat, int N) {
    int n = blockIdx.x * 8 + (threadIdx.x >> 5);
    if (n >= N) return;
    int lane = threadIdx.x & 31;
    int b = g_rowptr[n];
    int eend = g_rowptr[n + 1];
    float4 acc = {0.f, 0.f, 0.f, 0.f};
    float ws = 0.f;
    int e = b;
    for (; e + 1 < eend; e += 2) {
        uint2 p0 = g_epack[e];
        uint2 p1 = g_epack[e + 1];
        float w0 = __uint_as_float(p0.y);
        float w1 = __uint_as_float(p1.y);
        float4 v0 = __ldg((const float4*)feat + (size_t)p0.x * 32 + lane);
        float4 v1 = __ldg((const float4*)feat + (size_t)p1.x * 32 + lane);
        acc.x += w0 * v0.x + w1 * v1.x;
        acc.y += w0 * v0.y + w1 * v1.y;
        acc.z += w0 * v0.z + w1 * v1.z;
        acc.w += w0 * v0.w + w1 * v1.w;
        ws += w0 + w1;
    }
    if (e < eend) {
        uint2 p0 = g_epack[e];
        float w0 = __uint_as_float(p0.y);
        float4 v0 = __ldg((const float4*)feat + (size_t)p0.x * 32 + lane);
        acc.x += w0 * v0.x;
        acc.y += w0 * v0.y;
        acc.z += w0 * v0.z;
        acc.w += w0 * v0.w;
        ws += w0;
    }
    float inv = 1.0f / (ws + 1e-8f);   // ws is warp-uniform
    acc.x *= inv; acc.y *= inv; acc.z *= inv; acc.w *= inv;
    uint32_t h0, l0, h1, l1;
    cvt_hilo_fast(make_float2(acc.x, acc.y), h0, l0);
    cvt_hilo_fast(make_float2(acc.z, acc.w), h1, l1);
    ((uint2*)g_nhi)[(size_t)n * 32 + lane] = make_uint2(h0, h1);
    ((uint2*)g_nlo)[(size_t)n * 32 + lane] = make_uint2(l0, l1);
}

// ---------------- kernel 6: pipelined mma.sync GEMM ------------------------
// 512 threads (16 warps: 8 M x 2 N), tile 128x128, K=256 in 4 chunks of 64.
// Chunks 0-1: convert fp32 feat on the fly. Chunks 2-3: copy bf16 planes.
#define XS_STRIDE 36
#define XBUF_U32  (128 * XS_STRIDE)          // 4608 u32 per (hi|lo) plane
#define GEMM_SMEM (2 * 2 * XBUF_U32 * 4)     // 73728 bytes

__global__ void __launch_bounds__(512)
k_gemm_mma(const float* __restrict__ feat,
           const float* __restrict__ b_self,
           const float* __restrict__ bias,
           float* __restrict__ out,
           int N) {
    extern __shared__ uint32_t sx[];
    int tid  = threadIdx.x;
    int wid  = tid >> 5;
    int lane = tid & 31;
    int wm   = wid & 7;
    int wn   = wid >> 3;
    int n0   = blockIdx.x * 128;
    int g    = lane >> 2;
    int c    = lane & 3;

    float acc[8][4];
#pragma unroll
    for (int nt = 0; nt < 8; ++nt)
#pragma unroll
        for (int q = 0; q < 4; ++q) acc[nt][q] = 0.f;

    float2 pf[8];     // fp32 prefetch (chunks 0-1)
    uint4  pp[2][2];  // plane prefetch (chunks 2-3): [it][hi/lo]

    auto stage_load = [&](int kc) {
        if (kc < 2) {
            int colbase = (kc & 1) * 32;
#pragma unroll
            for (int it = 0; it < 8; ++it) {
                int idx = tid + it * 512;
                int row = idx >> 5, pc = idx & 31;
                int gn = n0 + row;
                pf[it] = (gn < N) ? ((const float2*)feat)[(size_t)gn * 64 + colbase + pc]
                                  : make_float2(0.f, 0.f);
            }
        } else {
            const uint4* ph = (const uint4*)g_nhi;
            const uint4* pl = (const uint4*)g_nlo;
            int cb4 = (kc & 1) * 8;
#pragma unroll
            for (int it = 0; it < 2; ++it) {
                int idx = tid + it * 512;
                int row = idx >> 3, qc = idx & 7;
                int gn = n0 + row;
                if (gn < N) {
                    size_t o = (size_t)gn * 16 + cb4 + qc;
                    pp[it][0] = ph[o];
                    pp[it][1] = pl[o];
                } else {
                    pp[it][0] = make_uint4(0, 0, 0, 0);
                    pp[it][1] = make_uint4(0, 0, 0, 0);
                }
            }
        }
    };
    auto stage_store = [&](int kc, uint32_t* bh, uint32_t* bl) {
        if (kc < 2) {
#pragma unroll
            for (int it = 0; it < 8; ++it) {
                int idx = tid + it * 512;
                int row = idx >> 5, pc = idx & 31;
                uint32_t hi, lo;
                cvt_hilo_fast(pf[it], hi, lo);
                bh[row * XS_STRIDE + pc] = hi;
                bl[row * XS_STRIDE + pc] = lo;
            }
        } else {
#pragma unroll
            for (int it = 0; it < 2; ++it) {
                int idx = tid + it * 512;
                int row = idx >> 3, qc = idx & 7;
                *(uint4*)(bh + row * XS_STRIDE + qc * 4) = pp[it][0];
                *(uint4*)(bl + row * XS_STRIDE + qc * 4) = pp[it][1];
            }
        }
    };
    auto compute = [&](int kc, const uint32_t* bh, const uint32_t* bl) {
#pragma unroll
        for (int j = 0; j < 4; ++j) {
            uint32_t ahi[4], alo[4];
            int r0 = (wm * 16 + g) * XS_STRIDE + j * 8;
            ahi[0] = bh[r0 + c];
            ahi[1] = bh[r0 + 8 * XS_STRIDE + c];
            ahi[2] = bh[r0 + c + 4];
            ahi[3] = bh[r0 + 8 * XS_STRIDE + c + 4];
            alo[0] = bl[r0 + c];
            alo[1] = bl[r0 + 8 * XS_STRIDE + c];
            alo[2] = bl[r0 + c + 4];
            alo[3] = bl[r0 + 8 * XS_STRIDE + c + 4];
            int ks = kc * 4 + j;
#pragma unroll
            for (int nt = 0; nt < 8; ++nt) {
                uint2 bhi = __ldg(&g_wfrag[((0 * 16 + ks) * 16 + wn * 8 + nt) * 32 + lane]);
                uint2 blo = __ldg(&g_wfrag[((1 * 16 + ks) * 16 + wn * 8 + nt) * 32 + lane]);
                MMA16816(acc[nt], ahi, bhi.x, bhi.y);
                MMA16816(acc[nt], ahi, blo.x, blo.y);
                MMA16816(acc[nt], alo, bhi.x, bhi.y);
            }
        }
    };

    uint32_t* buf0 = sx;
    uint32_t* buf1 = sx + 2 * XBUF_U32;

    stage_load(0);
    stage_store(0, buf0, buf0 + XBUF_U32);
    __syncthreads();

#pragma unroll
    for (int kc = 0; kc < 4; ++kc) {
        uint32_t* cb = (kc & 1) ? buf1 : buf0;
        uint32_t* nb = (kc & 1) ? buf0 : buf1;
        if (kc < 3) stage_load(kc + 1);
        compute(kc, cb, cb + XBUF_U32);
        if (kc < 3) {
            stage_store(kc + 1, nb, nb + XBUF_U32);
            __syncthreads();
        }
    }

    // ---- epilogue: bias + relu, float2 stores ----
    float2 bsum[8];
#pragma unroll
    for (int nt = 0; nt < 8; ++nt) {
        int p = wn * 32 + nt * 4 + c;
        float2 b1 = __ldg((const float2*)b_self + p);
        float2 b2 = __ldg((const float2*)bias + p);
        bsum[nt].x = b1.x + b2.x;
        bsum[nt].y = b1.y + b2.y;
    }
    int r0 = n0 + wm * 16 + g;
    int r1 = r0 + 8;
#pragma unroll
    for (int nt = 0; nt < 8; ++nt) {
        int p = wn * 32 + nt * 4 + c;
        if (r0 < N) {
            float2 v;
            v.x = fmaxf(acc[nt][0] + bsum[nt].x, 0.f);
            v.y = fmaxf(acc[nt][1] + bsum[nt].y, 0.f);
            ((float2*)out)[(size_t)r0 * 64 + p] = v;
        }
        if (r1 < N) {
            float2 v;
            v.x = fmaxf(acc[nt][2] + bsum[nt].x, 0.f);
            v.y = fmaxf(acc[nt][3] + bsum[nt].y, 0.f);
            ((float2*)out)[(size_t)r1 * 64 + p] = v;
        }
    }
}

// ---------------- kernel 7: BN column stats over out ----------------
__global__ void k_stats(const float* __restrict__ out, int N) {
    __shared__ float s1[256], s2[256];
    int tid = threadIdx.x;
    int c = tid & 127;
    int half = tid >> 7;
    int r0 = blockIdx.x * 512 + half;
    int r1 = min(N, blockIdx.x * 512 + 512);
    float s = 0.f, ss = 0.f;
    for (int r = r0; r < r1; r += 2) {
        float v = out[(size_t)r * 128 + c];
        s += v; ss += v * v;
    }
    s1[tid] = s; s2[tid] = ss;
    __syncthreads();
    if (tid < 128) {
        atomicAdd(&g_stats[c], s1[tid] + s1[tid + 128]);
        atomicAdd(&g_stats[128 + c], s2[tid] + s2[tid + 128]);
    }
}

// ---------------- kernel 8: apply BN (scale/shift computed in-block) -------
__global__ void k_apply(float* __restrict__ out, int n4,
                        const float* __restrict__ gamma,
                        const float* __restrict__ beta,
                        float invN) {
    __shared__ float4 ssc[32], ssh[32];
    int tid = threadIdx.x;
    if (tid < 32) {
        float4 sc, sh;
        float* scp = (float*)&sc;
        float* shp = (float*)&sh;
#pragma unroll
        for (int q = 0; q < 4; ++q) {
            int col = tid * 4 + q;
            float mu  = g_stats[col] * invN;
            float var = fmaxf(g_stats[128 + col] * invN - mu * mu, 0.f);
            float s   = __ldg(gamma + col) * rsqrtf(var + 1e-5f);
            scp[q] = s;
            shp[q] = __ldg(beta + col) - mu * s;
        }
        ssc[tid] = sc;
        ssh[tid] = sh;
    }
    __syncthreads();
    int i = blockIdx.x * blockDim.x + tid;
    if (i >= n4) return;
    int c = i & 31;
    float4 v  = ((float4*)out)[i];
    float4 sc = ssc[c];
    float4 sh = ssh[c];
    v.x = fmaf(v.x, sc.x, sh.x);
    v.y = fmaf(v.y, sc.y, sh.y);
    v.z = fmaf(v.z, sc.z, sh.z);
    v.w = fmaf(v.w, sc.w, sh.w);
    ((float4*)out)[i] = v;
}

// ---------------- launch ----------------
extern "C" void kernel_launch(void* const* d_in, const int* in_sizes, int n_in,
                              void* d_out, int out_size) {
    const float* feat   = (const float*)d_in[0];
    const int*   src    = (const int*)d_in[1];
    const int*   dst    = (const int*)d_in[2];
    const float* ew     = (const float*)d_in[3];
    const float* Wneigh = (const float*)d_in[4];
    const float* Wself  = (const float*)d_in[5];
    const float* b_self = (const float*)d_in[6];
    const float* bias   = (const float*)d_in[7];
    const float* gamma  = (const float*)d_in[8];
    const float* beta   = (const float*)d_in[9];
    float* out = (float*)d_out;

    int N = in_sizes[0] / 128;
    int E = in_sizes[1];

    cudaFuncSetAttribute(k_gemm_mma, cudaFuncAttributeMaxDynamicSharedMemorySize,
                         GEMM_SMEM);

    k_init<<<NSB + 64, 256>>>(Wneigh, Wself, N);
    k_hist<<<(E + 255) / 256, 256>>>(dst, E);
    k_scan1<<<NSB, SCAN_B>>>(N);
    k_scan23<<<NSB, SCAN_B>>>(N, E);
    k_place<<<(E + 255) / 256, 256>>>(src, dst, ew, E);
    k_agg<<<(N + 7) / 8, 256>>>(feat, N);
    k_gemm_mma<<<(N + 127) / 128, 512, GEMM_SMEM>>>(feat, b_self, bias, out, N);
    k_stats<<<(N + 511) / 512, 256>>>(out, N);
    k_apply<<<(N * 32 + 255) / 256, 256>>>(out, N * 32, gamma, beta,
                                           1.0f / (float)N);
}